// round 5
// baseline (speedup 1.0000x reference)
#include <cuda_runtime.h>
#include <math_constants.h>

#define NUM_VIEW 300
#define NPAIR    150   // view pairs

// Paired codebook layout. Pair j (views 2j, 2j+1):
//   g_pairA[j] = bits of {x0, x1, y0, y1}
//   g_pairB[j] = bits of {z0, z1, c0, c1}   where c = -|v|^2/2
__device__ ulonglong2 g_pairA[NPAIR];
__device__ ulonglong2 g_pairB[NPAIR];

__global__ void np_init_views_kernel() {
    int i = blockIdx.x * blockDim.x + threadIdx.x;
    if (i < NUM_VIEW) {
        // Match numpy float64 construction exactly, then cast to float32.
        double di  = (double)i;
        double zi  = (2.0 * di + 1.0) / (double)NUM_VIEW - 1.0;
        double r2  = 1.0 - zi * zi;
        if (r2 < 0.0) r2 = 0.0;
        double r   = sqrt(r2);
        const double PHI = (sqrt(5.0) - 1.0) * 0.5;
        double ang = 2.0 * di * CUDART_PI * PHI;
        double s, c;
        sincos(ang, &s, &c);
        float xf = (float)(r * c);
        float yf = (float)(r * s);
        float zf = (float)zi;
        float vv = __fadd_rn(__fadd_rn(__fmul_rn(xf, xf), __fmul_rn(yf, yf)),
                             __fmul_rn(zf, zf));
        float cf = -0.5f * vv;

        int j = i >> 1;
        int o = i & 1;
        float* fa = (float*)&g_pairA[j];
        float* fb = (float*)&g_pairB[j];
        fa[0 + o] = xf;
        fa[2 + o] = yf;
        fb[0 + o] = zf;
        fb[2 + o] = cf;
    }
}

__device__ __forceinline__ unsigned long long np_fma2(
        unsigned long long a, unsigned long long b, unsigned long long c) {
    unsigned long long d;
    asm("fma.rn.f32x2 %0, %1, %2, %3;" : "=l"(d) : "l"(a), "l"(b), "l"(c));
    return d;
}

__device__ __forceinline__ unsigned long long np_pack2(float lo, float hi) {
    unsigned long long d;
    asm("mov.b64 %0, {%1, %2};" : "=l"(d) : "f"(lo), "f"(hi));
    return d;
}

__device__ __forceinline__ void np_unpack2(float& lo, float& hi,
                                           unsigned long long v) {
    asm("mov.b64 {%0, %1}, %2;" : "=f"(lo), "=f"(hi) : "l"(v));
}

__device__ __forceinline__ void np_merge_max(float& s0, int& i0, float s1, int i1) {
    // first-max (lowest index) wins on ties — matches argmin-first semantics
    if (s1 > s0 || (s1 == s0 && i1 < i0)) { s0 = s1; i0 = i1; }
}

// 2 threads per point. Lane h in {0,1} scans pairs [h*75, h*75+75).
// argmin(|n-v|^2) == argmax(dot(n,v) - |v|^2/2): packed f32x2 FMAs.
// MODE 0: indices written as float32 (output = 13*P floats)
// MODE 1: indices written as int64 bit-pattern (output = 14*P float slots)
template <int MODE>
__global__ void __launch_bounds__(448)
np_main_kernel(const float* __restrict__ normals,
               const int*   __restrict__ idxs,
               float*       __restrict__ out,
               int N, int S, int logS, int P) {
    __shared__ ulonglong2 sA[NPAIR];
    __shared__ ulonglong2 sB[NPAIR];
    for (int i = threadIdx.x; i < NPAIR; i += blockDim.x) {
        sA[i] = g_pairA[i];
        sB[i] = g_pairB[i];
    }
    __syncthreads();

    int t = blockIdx.x * blockDim.x + threadIdx.x;
    int p = t >> 1;
    int h = t & 1;
    if (p >= P) return;

    int b   = (logS >= 0) ? (p >> logS) : (p / S);
    int idx = idxs[p];
    const float* nptr = normals + ((long long)b * N + idx) * 3;
    float nx = __ldg(nptr + 0);
    float ny = __ldg(nptr + 1);
    float nz = __ldg(nptr + 2);

    unsigned long long pnx = np_pack2(nx, nx);
    unsigned long long pny = np_pack2(ny, ny);
    unsigned long long pnz = np_pack2(nz, nz);

    // --- argmax over this lane's 75 pairs: 3 pairs (6 views) per iteration ---
    const int h75 = h * 75;
    float bl0 = -CUDART_INF_F, bl1 = -CUDART_INF_F, bl2 = -CUDART_INF_F;
    float bh0 = -CUDART_INF_F, bh1 = -CUDART_INF_F, bh2 = -CUDART_INF_F;
    int   kl0 = 0, kl1 = 0, kl2 = 0, kh0 = 0, kh1 = 0, kh2 = 0;

#pragma unroll 5
    for (int k = 0; k < 25; k++) {
        int j = h75 + k * 3;
        ulonglong2 A0 = sA[j + 0], B0 = sB[j + 0];
        ulonglong2 A1 = sA[j + 1], B1 = sB[j + 1];
        ulonglong2 A2 = sA[j + 2], B2 = sB[j + 2];

        unsigned long long s0 = np_fma2(pnx, A0.x,
                                 np_fma2(pny, A0.y, np_fma2(pnz, B0.x, B0.y)));
        unsigned long long s1 = np_fma2(pnx, A1.x,
                                 np_fma2(pny, A1.y, np_fma2(pnz, B1.x, B1.y)));
        unsigned long long s2 = np_fma2(pnx, A2.x,
                                 np_fma2(pny, A2.y, np_fma2(pnz, B2.x, B2.y)));

        float f0l, f0h, f1l, f1h, f2l, f2h;
        np_unpack2(f0l, f0h, s0);
        np_unpack2(f1l, f1h, s1);
        np_unpack2(f2l, f2h, s2);

        // strict > keeps first-win; record only loop counter k (reg reuse)
        if (f0l > bl0) { bl0 = f0l; kl0 = k; }
        if (f0h > bh0) { bh0 = f0h; kh0 = k; }
        if (f1l > bl1) { bl1 = f1l; kl1 = k; }
        if (f1h > bh1) { bh1 = f1h; kh1 = k; }
        if (f2l > bl2) { bl2 = f2l; kl2 = k; }
        if (f2h > bh2) { bh2 = f2h; kh2 = k; }
    }

    // reconstruct view indices: pair j = h75 + 3k + m; view = 2j (+1 for hi)
    int il0 = 2 * (h75 + 3 * kl0 + 0);
    int il1 = 2 * (h75 + 3 * kl1 + 1);
    int il2 = 2 * (h75 + 3 * kl2 + 2);
    int ih0 = 2 * (h75 + 3 * kh0 + 0) + 1;
    int ih1 = 2 * (h75 + 3 * kh1 + 1) + 1;
    int ih2 = 2 * (h75 + 3 * kh2 + 2) + 1;

    // merge 6 accumulators (index tie-break keeps exact first-win semantics)
    np_merge_max(bl0, il0, bh0, ih0);
    np_merge_max(bl1, il1, bh1, ih1);
    np_merge_max(bl2, il2, bh2, ih2);
    np_merge_max(bl0, il0, bl1, il1);
    np_merge_max(bl0, il0, bl2, il2);

    // merge across the lane pair
    float os = __shfl_xor_sync(0xffffffffu, bl0, 1);
    int   oi = __shfl_xor_sync(0xffffffffu, il0, 1);
    np_merge_max(bl0, il0, os, oi);
    int bi = il0;

    // --- rotation matrix from towards = -n, angle = 0 (R1 = I, rot = R2) ---
    float ax_x = -nx, ax_y = -ny, ax_z = -nz;
    float ay_x = -ax_y;   // = ny
    float ay_y =  ax_x;   // = -nx
    float ay_z = 0.0f;
    if (ay_x * ay_x + ay_y * ay_y + ay_z * ay_z == 0.0f) {
        ay_x = 0.0f; ay_y = 1.0f; ay_z = 0.0f;
    }
    float inva = 1.0f / sqrtf(ax_x * ax_x + ax_y * ax_y + ax_z * ax_z);
    ax_x *= inva; ax_y *= inva; ax_z *= inva;
    float invy = 1.0f / sqrtf(ay_x * ay_x + ay_y * ay_y + ay_z * ay_z);
    ay_x *= invy; ay_y *= invy; ay_z *= invy;
    float az_x = ax_y * ay_z - ax_z * ay_y;
    float az_y = ax_z * ay_x - ax_x * ay_z;
    float az_z = ax_x * ay_y - ax_y * ay_x;

    // --- outputs (stores split between the two lanes of the pair) ---
    float* out_xyz;
    float* out_rot;
    if (MODE == 0) {
        out_xyz = out + P;
        out_rot = out + P + 3 * (long long)P;
    } else {
        out_xyz = out + 2 * (long long)P;
        out_rot = out + 2 * (long long)P + 3 * (long long)P;
    }

    long long base3 = (long long)p * 3;
    long long base9 = (long long)p * 9;

    if (h == 0) {
        if (MODE == 0) {
            out[p] = (float)bi;
        } else {
            ((long long*)out)[p] = (long long)bi;
        }
        out_xyz[base3 + 0] = nx;
        out_xyz[base3 + 1] = ny;
        out_xyz[base3 + 2] = nz;
        // row-major [r][c]: col0 = ax, col1 = ay, col2 = az
        out_rot[base9 + 0] = ax_x;
        out_rot[base9 + 1] = ay_x;
        out_rot[base9 + 2] = az_x;
        out_rot[base9 + 3] = ax_y;
    } else {
        out_rot[base9 + 4] = ay_y;
        out_rot[base9 + 5] = az_y;
        out_rot[base9 + 6] = ax_z;
        out_rot[base9 + 7] = ay_z;
        out_rot[base9 + 8] = az_z;
    }
}

extern "C" void kernel_launch(void* const* d_in, const int* in_sizes, int n_in,
                              void* d_out, int out_size) {
    const float* normals = (const float*)d_in[0];
    const int*   idxs    = (const int*)d_in[1];
    float*       out     = (float*)d_out;

    const int B = 8;
    int P = in_sizes[1];            // B*S = 32768
    int S = P / B;                  // 4096
    int N = in_sizes[0] / (B * 3);  // 500000

    int logS = -1;
    if (S > 0 && (S & (S - 1)) == 0) {
        logS = 0;
        while ((1 << logS) < S) logS++;
    }

    np_init_views_kernel<<<75, 4>>>();

    // 2 lanes per point; one balanced wave: 148 blocks x 448 threads = 66304
    const int threads = 448;
    long long total = 2LL * P;
    int blocks = (int)((total + threads - 1) / threads);
    if (out_size == 14 * P) {
        np_main_kernel<1><<<blocks, threads>>>(normals, idxs, out, N, S, logS, P);
    } else {
        np_main_kernel<0><<<blocks, threads>>>(normals, idxs, out, N, S, logS, P);
    }
}